// round 14
// baseline (speedup 1.0000x reference)
#include <cuda_runtime.h>
#include <cuda_fp16.h>
#include <cstdint>

// Problem constants (fixed by the dataset)
#define NNODES 50000
#define LEV 2
#define RR 2
#define BLK (RR*LEV)          // 4 framelet blocks
#define NNZ 800000
#define F_IN 128
#define F_OUT 64
#define ACT_B (BLK - (LEV-1)) // 3 active blocks (block 0's y is never used)
#define ROWS_T (ACT_B * NNODES)   // 150000 (b, r) rows
#define EDGES_T (ACT_B * NNZ)     // 2400000 active edges
#define NB1 ((ROWS_T + 255) / 256)  // 586 level-1 scan blocks
#define GEMM_THREADS 800000         // 3125 blocks * 256
#define PADDED_E (EDGES_T + 3 * ROWS_T)   // 2,850,000 (pad-4 worst case)

// ---------------------------------------------------------------------------
// Scratch. h, y are fp16 (half2-packed): one row = 64 halves = 128 B = 8
// uint4. Edge list is PACKED AoS: edge = 4 B (uint16 col | fp16 val << 16);
// row segments padded to %4 so uint4 loads of 4 edges stay 16B-aligned.
//
// g_rank[e] = edge's rank within its (b,r) row (histogram atomic return).
// g_part holds RAW padded block totals (scan1); every consumer block scans
// them locally in smem (586 entries — cheap) instead of a scan2 launch.
// g_startF = finalized global row starts, written by scatter blocks 0..585.
//
// Cross-replay invariant: g_hist == 0 at entry. BSS zero-init covers the
// first run; spmm2_csr restores zero after its final read on every replay.
// ---------------------------------------------------------------------------
__device__ uint4  g_h[(size_t)NNODES * 8];     // 6.4 MB
__device__ uint4  g_y[(size_t)ROWS_T * 8];     // 19.2 MB
__device__ int    g_hist[ROWS_T];              // per-(b,r) nnz
__device__ int    g_start[ROWS_T];             // block-local padded excl prefix
__device__ int    g_startF[ROWS_T];            // finalized global row starts
__device__ int    g_part[1024];                // RAW padded block totals
__device__ int    g_rank[EDGES_T];             // 9.6 MB, edge rank within row
__device__ uint4  g_ep4[(PADDED_E + 3) / 4];   // packed edges, 11.4 MB
#define g_ep ((unsigned*)g_ep4)

__device__ __forceinline__ unsigned pack_h2(float a, float b) {
    __half2 h = __floats2half2_rn(a, b);
    return *reinterpret_cast<unsigned*>(&h);
}
__device__ __forceinline__ float2 unpack_h2(unsigned u) {
    __half2 h = *reinterpret_cast<__half2*>(&u);
    return __half22float2(h);
}
__device__ __forceinline__ unsigned pack_edge(int c, float v) {
    return (unsigned)c | ((unsigned)__half_as_ushort(__float2half_rn(v)) << 16);
}
__device__ __forceinline__ float edge_val(unsigned e) {
    return __half2float(__ushort_as_half((unsigned short)(e >> 16)));
}
__device__ __forceinline__ void accum8(float* acc, float v, uint4 hv) {
    const float2 f0 = unpack_h2(hv.x);
    const float2 f1 = unpack_h2(hv.y);
    const float2 f2 = unpack_h2(hv.z);
    const float2 f3 = unpack_h2(hv.w);
    acc[0] += v * f0.x; acc[1] += v * f0.y;
    acc[2] += v * f1.x; acc[3] += v * f1.y;
    acc[4] += v * f2.x; acc[5] += v * f2.y;
    acc[6] += v * f3.x; acc[7] += v * f3.y;
}

// ---------------------------------------------------------------------------
// h = x @ W (fp32 compute, fp16 store) + fused histogram with rank capture.
// ---------------------------------------------------------------------------
__global__ __launch_bounds__(256) void gemm_xw(const float* __restrict__ x,
                                               const float* __restrict__ w,
                                               const int*   __restrict__ rows) {
    const int t  = threadIdx.x;
    const int gt = blockIdx.x * 256 + t;

    __shared__ float4 ws[F_IN * (F_OUT/4)];   // 32 KB
    __shared__ float4 xs[16 * (F_IN/4)];      // 8 KB

    // 3 strided edges per thread (3 * 800000 == EDGES_T). Atomic return is
    // the edge's rank within its row; stored coalesced.
    #pragma unroll
    for (int s = 0; s < 3; s++) {
        const int e = gt + s * GEMM_THREADS;
        const int b = e / NNZ;
        const int i = e - b * NNZ;
        const int r = rows[(size_t)(b + 1) * NNZ + i];
        g_rank[e] = atomicAdd(&g_hist[b * NNODES + r], 1);
    }

    #pragma unroll
    for (int i = 0; i < 8; i++)
        ws[t + i * 256] = ((const float4*)w)[t + i * 256];

    const size_t row0 = (size_t)blockIdx.x * 16;
    #pragma unroll
    for (int i = 0; i < 2; i++)
        xs[t + i * 256] = ((const float4*)x)[row0 * (F_IN/4) + t + i * 256];

    __syncthreads();

    const int fi = t & 15;
    const int ri = t >> 4;
    float4 acc = make_float4(0.f, 0.f, 0.f, 0.f);

    #pragma unroll
    for (int k = 0; k < F_IN; k += 4) {
        const float4 xv = xs[ri * (F_IN/4) + (k >> 2)];
        const float4 w0 = ws[(k + 0) * 16 + fi];
        const float4 w1 = ws[(k + 1) * 16 + fi];
        const float4 w2 = ws[(k + 2) * 16 + fi];
        const float4 w3 = ws[(k + 3) * 16 + fi];
        acc.x += xv.x * w0.x + xv.y * w1.x + xv.z * w2.x + xv.w * w3.x;
        acc.y += xv.x * w0.y + xv.y * w1.y + xv.z * w2.y + xv.w * w3.y;
        acc.z += xv.x * w0.z + xv.y * w1.z + xv.z * w2.z + xv.w * w3.z;
        acc.w += xv.x * w0.w + xv.y * w1.w + xv.z * w2.w + xv.w * w3.w;
    }
    uint2 p;
    p.x = pack_h2(acc.x, acc.y);
    p.y = pack_h2(acc.z, acc.w);
    ((uint2*)g_h)[(row0 + ri) * 16 + fi] = p;
}

// ---------------------------------------------------------------------------
// scan1: block-local exclusive prefix of padded lengths ((len+3)&~3);
// writes RAW padded block totals to g_part (no global scan needed here).
// ---------------------------------------------------------------------------
__global__ __launch_bounds__(256) void scan1() {
    __shared__ int wsum[8];
    const int t = threadIdx.x;
    const int lane = t & 31;
    const int wid = t >> 5;
    const int idx = blockIdx.x * 256 + t;
    const int v  = (idx < ROWS_T) ? g_hist[idx] : 0;
    const int pv = (v + 3) & ~3;

    int x = pv;
    #pragma unroll
    for (int off = 1; off < 32; off <<= 1) {
        const int n = __shfl_up_sync(0xffffffffu, x, off);
        if (lane >= off) x += n;
    }
    if (lane == 31) wsum[wid] = x;
    __syncthreads();
    if (t < 8) {
        const int orig = wsum[t];
        int s = orig;
        #pragma unroll
        for (int off = 1; off < 8; off <<= 1) {
            const int n = __shfl_up_sync(0x000000ffu, s, off);
            if (t >= off) s += n;
        }
        wsum[t] = s - orig;
    }
    __syncthreads();
    const int ex = x - pv + wsum[wid];
    if (idx < ROWS_T) g_start[idx] = ex;
    if (t == 255) g_part[blockIdx.x] = ex + pv;   // raw padded block total
}

// ---------------------------------------------------------------------------
// Local exclusive scan of the 586 raw block totals into smem (s_part).
// Each thread owns 3 consecutive entries; block scan over per-thread sums.
// ---------------------------------------------------------------------------
__device__ __forceinline__ void local_scan_part(int* s_part, int t) {
    __shared__ int wsum[8];
    const int lane = t & 31;
    const int wid = t >> 5;
    const int i0 = t * 3;
    const int a0 = (i0 + 0 < NB1) ? g_part[i0 + 0] : 0;
    const int a1 = (i0 + 1 < NB1) ? g_part[i0 + 1] : 0;
    const int a2 = (i0 + 2 < NB1) ? g_part[i0 + 2] : 0;
    const int mysum = a0 + a1 + a2;

    int x = mysum;
    #pragma unroll
    for (int off = 1; off < 32; off <<= 1) {
        const int n = __shfl_up_sync(0xffffffffu, x, off);
        if (lane >= off) x += n;
    }
    if (lane == 31) wsum[wid] = x;
    __syncthreads();
    if (t < 8) {
        const int orig = wsum[t];
        int s = orig;
        #pragma unroll
        for (int off = 1; off < 8; off <<= 1) {
            const int n = __shfl_up_sync(0x000000ffu, s, off);
            if (t >= off) s += n;
        }
        wsum[t] = s - orig;
    }
    __syncthreads();
    const int ex = x - mysum + wsum[wid];        // exclusive over thread sums
    if (i0 + 0 < 768) s_part[i0 + 0] = ex;
    if (i0 + 1 < 768) s_part[i0 + 1] = ex + a0;
    if (i0 + 2 < 768) s_part[i0 + 2] = ex + a0 + a1;
    __syncthreads();
}

// ---------------------------------------------------------------------------
// Scatter: ATOMIC-FREE. pos = g_start[bk] + s_part[bk>>8] + rank[e].
// Each block first scans g_part locally (smem). Blocks 0..585 additionally
// publish finalized row starts g_startF for the SpMM kernels.
// ---------------------------------------------------------------------------
__global__ __launch_bounds__(256) void scatter(const float* __restrict__ vals,
                                               const int*   __restrict__ rows,
                                               const int*   __restrict__ cols) {
    __shared__ int s_part[768];
    const int t = threadIdx.x;
    local_scan_part(s_part, t);

    // Publish finalized starts (one 256-row chunk per low-numbered block).
    const int j = blockIdx.x;
    if (j < NB1) {
        const int idx = j * 256 + t;
        if (idx < ROWS_T) g_startF[idx] = g_start[idx] + s_part[j];
    }

    const int p = blockIdx.x * 256 + t;
    if (p >= EDGES_T / 4) return;
    const int4   rp = ((const int4*)(rows + NNZ))[p];
    const int4   cp = ((const int4*)(cols + NNZ))[p];
    const float4 vp = ((const float4*)(vals + NNZ))[p];
    const int4   kp = ((const int4*)g_rank)[p];
    const int base = ((4 * p) / NNZ) * NNODES;   // quad never crosses a block

    const int bk0 = base + rp.x;
    const int bk1 = base + rp.y;
    const int bk2 = base + rp.z;
    const int bk3 = base + rp.w;
    g_ep[g_start[bk0] + s_part[bk0 >> 8] + kp.x] = pack_edge(cp.x, vp.x);
    g_ep[g_start[bk1] + s_part[bk1 >> 8] + kp.y] = pack_edge(cp.y, vp.y);
    g_ep[g_start[bk2] + s_part[bk2 >> 8] + kp.z] = pack_edge(cp.z, vp.z);
    g_ep[g_start[bk3] + s_part[bk3 >> 8] + kp.w] = pack_edge(cp.w, vp.w);
}

// ---------------------------------------------------------------------------
// SpMM-1 (CSR gather, 8-edge batched): y[b][r] = filt * sum v_e * h[c_e]
// Launch #4 -> profiled.
// ---------------------------------------------------------------------------
__global__ __launch_bounds__(256) void spmm1_csr(const float* __restrict__ filt) {
    const int gid = blockIdx.x * 256 + threadIdx.x;
    const int row = gid >> 3;
    if (row >= ROWS_T) return;
    const int q = gid & 7;
    const int beg = g_startF[row];
    const int len = g_hist[row];
    const int b = row / NNODES;
    const int r = row - b * NNODES;

    float acc[8];
    #pragma unroll
    for (int k = 0; k < 8; k++) acc[k] = 0.f;

    const unsigned* ep = g_ep + beg;
    int j = 0;
    for (; j + 8 <= len; j += 8) {
        const uint4 ea = *(const uint4*)(ep + j);
        const uint4 eb = *(const uint4*)(ep + j + 4);
        const uint4 h0 = g_h[(size_t)(ea.x & 0xffffu) * 8 + q];
        const uint4 h1 = g_h[(size_t)(ea.y & 0xffffu) * 8 + q];
        const uint4 h2 = g_h[(size_t)(ea.z & 0xffffu) * 8 + q];
        const uint4 h3 = g_h[(size_t)(ea.w & 0xffffu) * 8 + q];
        const uint4 h4 = g_h[(size_t)(eb.x & 0xffffu) * 8 + q];
        const uint4 h5 = g_h[(size_t)(eb.y & 0xffffu) * 8 + q];
        const uint4 h6 = g_h[(size_t)(eb.z & 0xffffu) * 8 + q];
        const uint4 h7 = g_h[(size_t)(eb.w & 0xffffu) * 8 + q];
        accum8(acc, edge_val(ea.x), h0);
        accum8(acc, edge_val(ea.y), h1);
        accum8(acc, edge_val(ea.z), h2);
        accum8(acc, edge_val(ea.w), h3);
        accum8(acc, edge_val(eb.x), h4);
        accum8(acc, edge_val(eb.y), h5);
        accum8(acc, edge_val(eb.z), h6);
        accum8(acc, edge_val(eb.w), h7);
    }
    for (; j + 4 <= len; j += 4) {
        const uint4 ea = *(const uint4*)(ep + j);
        const uint4 h0 = g_h[(size_t)(ea.x & 0xffffu) * 8 + q];
        const uint4 h1 = g_h[(size_t)(ea.y & 0xffffu) * 8 + q];
        const uint4 h2 = g_h[(size_t)(ea.z & 0xffffu) * 8 + q];
        const uint4 h3 = g_h[(size_t)(ea.w & 0xffffu) * 8 + q];
        accum8(acc, edge_val(ea.x), h0);
        accum8(acc, edge_val(ea.y), h1);
        accum8(acc, edge_val(ea.z), h2);
        accum8(acc, edge_val(ea.w), h3);
    }
    for (; j < len; j++) {
        const unsigned e = ep[j];
        const uint4 h = g_h[(size_t)(e & 0xffffu) * 8 + q];
        accum8(acc, edge_val(e), h);
    }

    const float f = filt[(size_t)(b + 1) * NNODES + r];
    uint4 o;
    o.x = pack_h2(f * acc[0], f * acc[1]);
    o.y = pack_h2(f * acc[2], f * acc[3]);
    o.z = pack_h2(f * acc[4], f * acc[5]);
    o.w = pack_h2(f * acc[6], f * acc[7]);
    g_y[(size_t)row * 8 + q] = o;
}

// ---------------------------------------------------------------------------
// SpMM-2 (CSR gather, 8-edge batched): out[r] = bias + sum_b sum v_e * y[b][c]
// Restores g_hist = 0 after the final read (warp-local slot; warp-wide LDG
// precedes lane-0's STG in program order; no other warp reads the slot).
// ---------------------------------------------------------------------------
__global__ __launch_bounds__(256) void spmm2_csr(float* __restrict__ out,
                                                 const float* __restrict__ bias) {
    const int gid = blockIdx.x * 256 + threadIdx.x;
    const int r = gid >> 3;
    if (r >= NNODES) return;
    const int q = gid & 7;

    float acc[8];
    {
        const float4 b0 = ((const float4*)bias)[q * 2 + 0];
        const float4 b1 = ((const float4*)bias)[q * 2 + 1];
        acc[0] = b0.x; acc[1] = b0.y; acc[2] = b0.z; acc[3] = b0.w;
        acc[4] = b1.x; acc[5] = b1.y; acc[6] = b1.z; acc[7] = b1.w;
    }

    #pragma unroll
    for (int b = 0; b < ACT_B; b++) {
        const int row = b * NNODES + r;
        const int beg = g_startF[row];
        const int len = g_hist[row];
        if (q == 0) g_hist[row] = 0;
        const size_t ybase = (size_t)b * NNODES * 8;
        const unsigned* ep = g_ep + beg;
        int j = 0;
        for (; j + 8 <= len; j += 8) {
            const uint4 ea = *(const uint4*)(ep + j);
            const uint4 eb = *(const uint4*)(ep + j + 4);
            const uint4 y0 = g_y[ybase + (size_t)(ea.x & 0xffffu) * 8 + q];
            const uint4 y1 = g_y[ybase + (size_t)(ea.y & 0xffffu) * 8 + q];
            const uint4 y2 = g_y[ybase + (size_t)(ea.z & 0xffffu) * 8 + q];
            const uint4 y3 = g_y[ybase + (size_t)(ea.w & 0xffffu) * 8 + q];
            const uint4 y4 = g_y[ybase + (size_t)(eb.x & 0xffffu) * 8 + q];
            const uint4 y5 = g_y[ybase + (size_t)(eb.y & 0xffffu) * 8 + q];
            const uint4 y6 = g_y[ybase + (size_t)(eb.z & 0xffffu) * 8 + q];
            const uint4 y7 = g_y[ybase + (size_t)(eb.w & 0xffffu) * 8 + q];
            accum8(acc, edge_val(ea.x), y0);
            accum8(acc, edge_val(ea.y), y1);
            accum8(acc, edge_val(ea.z), y2);
            accum8(acc, edge_val(ea.w), y3);
            accum8(acc, edge_val(eb.x), y4);
            accum8(acc, edge_val(eb.y), y5);
            accum8(acc, edge_val(eb.z), y6);
            accum8(acc, edge_val(eb.w), y7);
        }
        for (; j + 4 <= len; j += 4) {
            const uint4 ea = *(const uint4*)(ep + j);
            const uint4 y0 = g_y[ybase + (size_t)(ea.x & 0xffffu) * 8 + q];
            const uint4 y1 = g_y[ybase + (size_t)(ea.y & 0xffffu) * 8 + q];
            const uint4 y2 = g_y[ybase + (size_t)(ea.z & 0xffffu) * 8 + q];
            const uint4 y3 = g_y[ybase + (size_t)(ea.w & 0xffffu) * 8 + q];
            accum8(acc, edge_val(ea.x), y0);
            accum8(acc, edge_val(ea.y), y1);
            accum8(acc, edge_val(ea.z), y2);
            accum8(acc, edge_val(ea.w), y3);
        }
        for (; j < len; j++) {
            const unsigned e = ep[j];
            const uint4 yv = g_y[ybase + (size_t)(e & 0xffffu) * 8 + q];
            accum8(acc, edge_val(e), yv);
        }
    }
    float4* op = (float4*)(out + (size_t)r * F_OUT + q * 8);
    op[0] = make_float4(acc[0], acc[1], acc[2], acc[3]);
    op[1] = make_float4(acc[4], acc[5], acc[6], acc[7]);
}

// ---------------------------------------------------------------------------
// Launch: gemm(+hist+rank), scan1, scatter(+local scan2 + startF), spmm1, spmm2
// ---------------------------------------------------------------------------
extern "C" void kernel_launch(void* const* d_in, const int* in_sizes, int n_in,
                              void* d_out, int out_size) {
    const float* x    = (const float*)d_in[0];
    const float* wgt  = (const float*)d_in[1];
    const float* filt = (const float*)d_in[2];
    const float* bias = (const float*)d_in[3];
    const float* vals = (const float*)d_in[4];
    const int*   rows = (const int*)d_in[5];
    const int*   cols = (const int*)d_in[6];
    float* out = (float*)d_out;

    gemm_xw<<<NNODES / 16, 256>>>(x, wgt, rows);                   // #1
    scan1<<<NB1, 256>>>();                                         // #2
    scatter<<<(EDGES_T / 4 + 255) / 256, 256>>>(vals, rows, cols); // #3
    spmm1_csr<<<(ROWS_T * 8 + 255) / 256, 256>>>(filt);            // #4 (ncu)
    spmm2_csr<<<(NNODES * 8 + 255) / 256, 256>>>(out, bias);       // #5
}

// round 15
// speedup vs baseline: 1.1283x; 1.1283x over previous
#include <cuda_runtime.h>
#include <cuda_fp16.h>
#include <cstdint>

// Problem constants (fixed by the dataset)
#define NNODES 50000
#define LEV 2
#define RR 2
#define BLK (RR*LEV)          // 4 framelet blocks
#define NNZ 800000
#define F_IN 128
#define F_OUT 64
#define ACT_B (BLK - (LEV-1)) // 3 active blocks (block 0's y is never used)
#define ROWS_T (ACT_B * NNODES)   // 150000 (b, r) rows
#define EDGES_T (ACT_B * NNZ)     // 2400000 active edges
#define NB1 ((ROWS_T + 255) / 256)  // 586 level-1 scan blocks
#define PADDED_E2 (EDGES_T + ROWS_T)  // 2,550,000 (pad-2 worst case)

// ---------------------------------------------------------------------------
// Scratch (champion R6 layout + pad-2 edge segments for 16B-aligned batching).
// h, y fp16 (half2-packed): one row = 64 halves = 128 B = 8 uint4.
// Edge = int2 (col, val-as-fp32-bits): v needs NO conversion in the SpMMs.
// Row segments padded to even length so (int4*) loads of 2 edges are aligned.
// ---------------------------------------------------------------------------
__device__ uint4 g_h[(size_t)NNODES * 8];     // 6.4 MB
__device__ uint4 g_y[(size_t)ROWS_T * 8];     // 19.2 MB
__device__ int   g_hist[ROWS_T];              // per-(b,r) nnz
__device__ int   g_start[ROWS_T];             // block-local padded excl prefix
__device__ int   g_cursor[ROWS_T];            // scatter cursors (block-local)
__device__ int   g_part[1024];                // scan block partials (exclusive)
__device__ int4  g_ev4[(PADDED_E2 + 1) / 2];  // padded edges, 20.4 MB
#define g_ev ((int2*)g_ev4)

__device__ __forceinline__ unsigned pack_h2(float a, float b) {
    __half2 h = __floats2half2_rn(a, b);
    return *reinterpret_cast<unsigned*>(&h);
}
__device__ __forceinline__ float2 unpack_h2(unsigned u) {
    __half2 h = *reinterpret_cast<__half2*>(&u);
    return __half22float2(h);
}
__device__ __forceinline__ void accum8(float* acc, float v, uint4 hv) {
    const float2 f0 = unpack_h2(hv.x);
    const float2 f1 = unpack_h2(hv.y);
    const float2 f2 = unpack_h2(hv.z);
    const float2 f3 = unpack_h2(hv.w);
    acc[0] += v * f0.x; acc[1] += v * f0.y;
    acc[2] += v * f1.x; acc[3] += v * f1.y;
    acc[4] += v * f2.x; acc[5] += v * f2.y;
    acc[6] += v * f3.x; acc[7] += v * f3.y;
}

// ---------------------------------------------------------------------------
// Kernel 1: h = x @ W (fp32 compute, fp16 store) + zero g_hist (fused).
// ---------------------------------------------------------------------------
__global__ __launch_bounds__(256) void gemm_xw(const float* __restrict__ x,
                                               const float* __restrict__ w) {
    const int t = threadIdx.x;
    const int gt = blockIdx.x * 256 + t;     // 3125*256 = 800000 >= ROWS_T
    if (gt < ROWS_T) g_hist[gt] = 0;

    __shared__ float4 ws[F_IN * (F_OUT/4)];   // 32 KB
    __shared__ float4 xs[16 * (F_IN/4)];      // 8 KB

    #pragma unroll
    for (int i = 0; i < 8; i++)
        ws[t + i * 256] = ((const float4*)w)[t + i * 256];

    const size_t row0 = (size_t)blockIdx.x * 16;
    #pragma unroll
    for (int i = 0; i < 2; i++)
        xs[t + i * 256] = ((const float4*)x)[row0 * (F_IN/4) + t + i * 256];

    __syncthreads();

    const int fi = t & 15;
    const int ri = t >> 4;
    float4 acc = make_float4(0.f, 0.f, 0.f, 0.f);

    #pragma unroll
    for (int k = 0; k < F_IN; k += 4) {
        const float4 xv = xs[ri * (F_IN/4) + (k >> 2)];
        const float4 w0 = ws[(k + 0) * 16 + fi];
        const float4 w1 = ws[(k + 1) * 16 + fi];
        const float4 w2 = ws[(k + 2) * 16 + fi];
        const float4 w3 = ws[(k + 3) * 16 + fi];
        acc.x += xv.x * w0.x + xv.y * w1.x + xv.z * w2.x + xv.w * w3.x;
        acc.y += xv.x * w0.y + xv.y * w1.y + xv.z * w2.y + xv.w * w3.y;
        acc.z += xv.x * w0.z + xv.y * w1.z + xv.z * w2.z + xv.w * w3.z;
        acc.w += xv.x * w0.w + xv.y * w1.w + xv.z * w2.w + xv.w * w3.w;
    }
    uint2 p;
    p.x = pack_h2(acc.x, acc.y);
    p.y = pack_h2(acc.z, acc.w);
    ((uint2*)g_h)[(row0 + ri) * 16 + fi] = p;
}

// ---------------------------------------------------------------------------
// hist_build: 2 edges per thread, vectorized index loads.
// ---------------------------------------------------------------------------
__global__ __launch_bounds__(256) void hist_build(const int* __restrict__ rows) {
    const int p = blockIdx.x * 256 + threadIdx.x;
    if (p >= EDGES_T / 2) return;
    const int2 rp = ((const int2*)(rows + NNZ))[p];
    const int b0 = (2 * p) / NNZ;
    atomicAdd(&g_hist[b0 * NNODES + rp.x], 1);
    atomicAdd(&g_hist[b0 * NNODES + rp.y], 1);
}

// ---------------------------------------------------------------------------
// scan1: block-local exclusive prefix of PADDED lengths ((len+1)&~1);
// seeds cursors; padded block totals to g_part.
// ---------------------------------------------------------------------------
__global__ __launch_bounds__(256) void scan1() {
    __shared__ int s[256];
    const int t = threadIdx.x;
    const int idx = blockIdx.x * 256 + t;
    const int v  = (idx < ROWS_T) ? g_hist[idx] : 0;
    const int pv = (v + 1) & ~1;             // pad each row to even length
    s[t] = pv;
    __syncthreads();
    #pragma unroll
    for (int off = 1; off < 256; off <<= 1) {
        const int a = (t >= off) ? s[t - off] : 0;
        __syncthreads();
        s[t] += a;
        __syncthreads();
    }
    if (idx < ROWS_T) {
        const int ex = s[t] - pv;
        g_start[idx]  = ex;
        g_cursor[idx] = ex;
    }
    if (t == 255) g_part[blockIdx.x] = s[t];
}

// ---------------------------------------------------------------------------
// scan2: single block exclusive-scans the block totals (guarded: stale
// g_part entries persist across graph replays).
// ---------------------------------------------------------------------------
__global__ __launch_bounds__(1024) void scan2() {
    __shared__ int s[1024];
    const int t = threadIdx.x;
    const int v = (t < NB1) ? g_part[t] : 0;
    s[t] = v;
    __syncthreads();
    #pragma unroll
    for (int off = 1; off < 1024; off <<= 1) {
        const int a = (t >= off) ? s[t - off] : 0;
        __syncthreads();
        s[t] += a;
        __syncthreads();
    }
    if (t < NB1) g_part[t] = s[t] - v;
}

// ---------------------------------------------------------------------------
// Scatter: 2 edges per thread; int2 edge stores (v kept as raw fp32 bits).
// ---------------------------------------------------------------------------
__global__ __launch_bounds__(256) void scatter(const float* __restrict__ vals,
                                               const int*   __restrict__ rows,
                                               const int*   __restrict__ cols) {
    const int p = blockIdx.x * 256 + threadIdx.x;
    if (p >= EDGES_T / 2) return;
    const int2   rp = ((const int2*)(rows + NNZ))[p];
    const int2   cp = ((const int2*)(cols + NNZ))[p];
    const float2 vp = ((const float2*)(vals + NNZ))[p];
    const int base = ((2 * p) / NNZ) * NNODES;

    const int bk0 = base + rp.x;
    const int pos0 = atomicAdd(&g_cursor[bk0], 1) + g_part[bk0 >> 8];
    g_ev[pos0] = make_int2(cp.x, __float_as_int(vp.x));

    const int bk1 = base + rp.y;
    const int pos1 = atomicAdd(&g_cursor[bk1], 1) + g_part[bk1 >> 8];
    g_ev[pos1] = make_int2(cp.y, __float_as_int(vp.y));
}

// ---------------------------------------------------------------------------
// SpMM-1 (CSR gather, 4-edge batched): y[b][r] = filt * sum v_e * h[c_e]
// 8 lanes per row; lane owns one uint4 (8 halves). beg is even -> int4 edge
// loads (2 edges each) are 16B-aligned; 4 feature gathers in flight.
// ---------------------------------------------------------------------------
__global__ __launch_bounds__(256) void spmm1_csr(const float* __restrict__ filt) {
    const int gid = blockIdx.x * 256 + threadIdx.x;
    const int row = gid >> 3;
    if (row >= ROWS_T) return;
    const int q = gid & 7;
    const int beg = g_start[row] + g_part[row >> 8];
    const int len = g_hist[row];
    const int b = row / NNODES;
    const int r = row - b * NNODES;

    float acc[8];
    #pragma unroll
    for (int k = 0; k < 8; k++) acc[k] = 0.f;

    const int2* ev = g_ev + beg;
    int j = 0;
    for (; j + 4 <= len; j += 4) {
        const int4 e01 = *(const int4*)(ev + j);       // (c0,v0,c1,v1)
        const int4 e23 = *(const int4*)(ev + j + 2);   // (c2,v2,c3,v3)
        const uint4 h0 = g_h[(size_t)e01.x * 8 + q];
        const uint4 h1 = g_h[(size_t)e01.z * 8 + q];
        const uint4 h2 = g_h[(size_t)e23.x * 8 + q];
        const uint4 h3 = g_h[(size_t)e23.z * 8 + q];
        accum8(acc, __int_as_float(e01.y), h0);
        accum8(acc, __int_as_float(e01.w), h1);
        accum8(acc, __int_as_float(e23.y), h2);
        accum8(acc, __int_as_float(e23.w), h3);
    }
    for (; j + 2 <= len; j += 2) {
        const int4 e01 = *(const int4*)(ev + j);
        const uint4 h0 = g_h[(size_t)e01.x * 8 + q];
        const uint4 h1 = g_h[(size_t)e01.z * 8 + q];
        accum8(acc, __int_as_float(e01.y), h0);
        accum8(acc, __int_as_float(e01.w), h1);
    }
    for (; j < len; j++) {
        const int2 e = ev[j];
        const uint4 h = g_h[(size_t)e.x * 8 + q];
        accum8(acc, __int_as_float(e.y), h);
    }

    const float f = filt[(size_t)(b + 1) * NNODES + r];
    uint4 o;
    o.x = pack_h2(f * acc[0], f * acc[1]);
    o.y = pack_h2(f * acc[2], f * acc[3]);
    o.z = pack_h2(f * acc[4], f * acc[5]);
    o.w = pack_h2(f * acc[6], f * acc[7]);
    g_y[(size_t)row * 8 + q] = o;
}

// ---------------------------------------------------------------------------
// SpMM-2 (CSR gather, 4-edge batched): out[r] = bias + sum_b sum v_e * y[b][c]
// ---------------------------------------------------------------------------
__global__ __launch_bounds__(256) void spmm2_csr(float* __restrict__ out,
                                                 const float* __restrict__ bias) {
    const int gid = blockIdx.x * 256 + threadIdx.x;
    const int r = gid >> 3;
    if (r >= NNODES) return;
    const int q = gid & 7;

    float acc[8];
    {
        const float4 b0 = ((const float4*)bias)[q * 2 + 0];
        const float4 b1 = ((const float4*)bias)[q * 2 + 1];
        acc[0] = b0.x; acc[1] = b0.y; acc[2] = b0.z; acc[3] = b0.w;
        acc[4] = b1.x; acc[5] = b1.y; acc[6] = b1.z; acc[7] = b1.w;
    }

    #pragma unroll
    for (int b = 0; b < ACT_B; b++) {
        const int row = b * NNODES + r;
        const int beg = g_start[row] + g_part[row >> 8];
        const int len = g_hist[row];
        const size_t ybase = (size_t)b * NNODES * 8;
        const int2* ev = g_ev + beg;
        int j = 0;
        for (; j + 4 <= len; j += 4) {
            const int4 e01 = *(const int4*)(ev + j);
            const int4 e23 = *(const int4*)(ev + j + 2);
            const uint4 y0 = g_y[ybase + (size_t)e01.x * 8 + q];
            const uint4 y1 = g_y[ybase + (size_t)e01.z * 8 + q];
            const uint4 y2 = g_y[ybase + (size_t)e23.x * 8 + q];
            const uint4 y3 = g_y[ybase + (size_t)e23.z * 8 + q];
            accum8(acc, __int_as_float(e01.y), y0);
            accum8(acc, __int_as_float(e01.w), y1);
            accum8(acc, __int_as_float(e23.y), y2);
            accum8(acc, __int_as_float(e23.w), y3);
        }
        for (; j + 2 <= len; j += 2) {
            const int4 e01 = *(const int4*)(ev + j);
            const uint4 y0 = g_y[ybase + (size_t)e01.x * 8 + q];
            const uint4 y1 = g_y[ybase + (size_t)e01.z * 8 + q];
            accum8(acc, __int_as_float(e01.y), y0);
            accum8(acc, __int_as_float(e01.w), y1);
        }
        for (; j < len; j++) {
            const int2 e = ev[j];
            const uint4 yv = g_y[ybase + (size_t)e.x * 8 + q];
            accum8(acc, __int_as_float(e.y), yv);
        }
    }
    float4* op = (float4*)(out + (size_t)r * F_OUT + q * 8);
    op[0] = make_float4(acc[0], acc[1], acc[2], acc[3]);
    op[1] = make_float4(acc[4], acc[5], acc[6], acc[7]);
}

// ---------------------------------------------------------------------------
// Launch (champion R6 order): gemm(+zero), hist, scan1, scan2, scatter,
// spmm1, spmm2
// ---------------------------------------------------------------------------
extern "C" void kernel_launch(void* const* d_in, const int* in_sizes, int n_in,
                              void* d_out, int out_size) {
    const float* x    = (const float*)d_in[0];
    const float* wgt  = (const float*)d_in[1];
    const float* filt = (const float*)d_in[2];
    const float* bias = (const float*)d_in[3];
    const float* vals = (const float*)d_in[4];
    const int*   rows = (const int*)d_in[5];
    const int*   cols = (const int*)d_in[6];
    float* out = (float*)d_out;

    gemm_xw<<<NNODES / 16, 256>>>(x, wgt);                         // #1
    hist_build<<<(EDGES_T / 2 + 255) / 256, 256>>>(rows);          // #2
    scan1<<<NB1, 256>>>();                                         // #3
    scan2<<<1, 1024>>>();                                          // #4
    scatter<<<(EDGES_T / 2 + 255) / 256, 256>>>(vals, rows, cols); // #5
    spmm1_csr<<<(ROWS_T * 8 + 255) / 256, 256>>>(filt);            // #6
    spmm2_csr<<<(NNODES * 8 + 255) / 256, 256>>>(out, bias);       // #7
}